// round 1
// baseline (speedup 1.0000x reference)
#include <cuda_runtime.h>
#include <cuda_bf16.h>
#include <cstdint>

#define M_DIM 8192
#define N_DIM 4096
#define K_DIM 4096

// ---------------- scratch (no allocations allowed) ----------------
__device__ float g_absmax[2];                         // [0]=x, [1]=W
__device__ __nv_bfloat16 g_qx[(size_t)M_DIM * K_DIM]; // 64 MB
__device__ __nv_bfloat16 g_qw[(size_t)N_DIM * K_DIM]; // 32 MB

// ---------------- init ----------------
__global__ void init_kernel() {
    if (threadIdx.x < 2) g_absmax[threadIdx.x] = 0.0f;
}

// ---------------- absmax reduction ----------------
__global__ void absmax_kernel(const float4* __restrict__ p, int n4, int slot) {
    float m = 0.0f;
    int stride = gridDim.x * blockDim.x;
    for (int i = blockIdx.x * blockDim.x + threadIdx.x; i < n4; i += stride) {
        float4 v = p[i];
        m = fmaxf(m, fmaxf(fmaxf(fabsf(v.x), fabsf(v.y)),
                           fmaxf(fabsf(v.z), fabsf(v.w))));
    }
    #pragma unroll
    for (int o = 16; o; o >>= 1) m = fmaxf(m, __shfl_xor_sync(0xFFFFFFFFu, m, o));
    __shared__ float sm[32];
    if ((threadIdx.x & 31) == 0) sm[threadIdx.x >> 5] = m;
    __syncthreads();
    if (threadIdx.x < 32) {
        m = (threadIdx.x < (blockDim.x >> 5)) ? sm[threadIdx.x] : 0.0f;
        #pragma unroll
        for (int o = 16; o; o >>= 1) m = fmaxf(m, __shfl_xor_sync(0xFFFFFFFFu, m, o));
        if (threadIdx.x == 0)
            atomicMax((unsigned int*)&g_absmax[slot], __float_as_uint(m));
    }
}

// ---------------- quantize to integer-valued bf16 ----------------
__global__ void quant_x_kernel(const float4* __restrict__ in, int n4) {
    int i = blockIdx.x * blockDim.x + threadIdx.x;
    if (i >= n4) return;
    float s = g_absmax[0] / 127.0f;
    float4 v = in[i];
    float q0 = fminf(fmaxf(rintf(v.x / s), -128.0f), 127.0f);
    float q1 = fminf(fmaxf(rintf(v.y / s), -128.0f), 127.0f);
    float q2 = fminf(fmaxf(rintf(v.z / s), -128.0f), 127.0f);
    float q3 = fminf(fmaxf(rintf(v.w / s), -128.0f), 127.0f);
    __nv_bfloat162* o2 = (__nv_bfloat162*)(g_qx + (size_t)i * 4);
    o2[0] = __floats2bfloat162_rn(q0, q1);
    o2[1] = __floats2bfloat162_rn(q2, q3);
}

__global__ void quant_w_kernel(const float4* __restrict__ in, int n4) {
    int i = blockIdx.x * blockDim.x + threadIdx.x;
    if (i >= n4) return;
    float s = g_absmax[1] / 127.0f;
    float4 v = in[i];
    float q0 = fminf(fmaxf(rintf(v.x / s), -127.0f), 127.0f);
    float q1 = fminf(fmaxf(rintf(v.y / s), -127.0f), 127.0f);
    float q2 = fminf(fmaxf(rintf(v.z / s), -127.0f), 127.0f);
    float q3 = fminf(fmaxf(rintf(v.w / s), -127.0f), 127.0f);
    __nv_bfloat162* o2 = (__nv_bfloat162*)(g_qw + (size_t)i * 4);
    o2[0] = __floats2bfloat162_rn(q0, q1);
    o2[1] = __floats2bfloat162_rn(q2, q3);
}

// ---------------- GEMM: C[M,N] = qx[M,K] * qw[N,K]^T (both K-major) ----------------
#define BM 128
#define BN 128
#define BK 32
#define LDT 40  // padded smem row stride (bf16 elems); 80B rows -> conflict-free ldmatrix

__device__ __forceinline__ unsigned smem_u32(const void* p) {
    return (unsigned)__cvta_generic_to_shared(p);
}

__device__ __forceinline__ void ldsm4(unsigned r[4], unsigned addr) {
    asm volatile("ldmatrix.sync.aligned.m8n8.x4.shared.b16 {%0,%1,%2,%3}, [%4];"
                 : "=r"(r[0]), "=r"(r[1]), "=r"(r[2]), "=r"(r[3])
                 : "r"(addr));
}

__device__ __forceinline__ void mma_bf16(float c[4],
                                         unsigned a0, unsigned a1, unsigned a2, unsigned a3,
                                         unsigned b0, unsigned b1) {
    asm volatile(
        "mma.sync.aligned.m16n8k16.row.col.f32.bf16.bf16.f32 "
        "{%0,%1,%2,%3}, {%4,%5,%6,%7}, {%8,%9}, {%0,%1,%2,%3};"
        : "+f"(c[0]), "+f"(c[1]), "+f"(c[2]), "+f"(c[3])
        : "r"(a0), "r"(a1), "r"(a2), "r"(a3), "r"(b0), "r"(b1));
}

__global__ __launch_bounds__(256, 1) void gemm_kernel(float* __restrict__ C,
                                                      const float* __restrict__ bias) {
    __shared__ __nv_bfloat16 sA[2][BM * LDT];
    __shared__ __nv_bfloat16 sB[2][BN * LDT];

    const int tid  = threadIdx.x;
    const int lane = tid & 31;
    const int warp = tid >> 5;
    const int wm   = warp >> 2;   // 0..1  (64 rows each)
    const int wn   = warp & 3;    // 0..3  (32 cols each)
    const int bm0  = blockIdx.y * BM;
    const int bn0  = blockIdx.x * BN;

    const __nv_bfloat16* gA = g_qx + (size_t)bm0 * K_DIM;
    const __nv_bfloat16* gB = g_qw + (size_t)bn0 * K_DIM;

    float acc[4][4][4];
    #pragma unroll
    for (int mi = 0; mi < 4; ++mi)
        #pragma unroll
        for (int ni = 0; ni < 4; ++ni)
            #pragma unroll
            for (int r = 0; r < 4; ++r) acc[mi][ni][r] = 0.0f;

    // 16B-chunk load mapping: 128 rows x 4 chunks; thread does rows tid/4 and tid/4+64
    const int lrow = tid >> 2;
    const int lcol = (tid & 3) * 8;

    auto load_tile = [&](int kt, int buf) {
        const int k0 = kt * BK;
        {
            const __nv_bfloat16* src = gA + (size_t)lrow * K_DIM + k0 + lcol;
            unsigned dst = smem_u32(&sA[buf][lrow * LDT + lcol]);
            asm volatile("cp.async.cg.shared.global [%0], [%1], 16;\n" :: "r"(dst), "l"(src));
            src += (size_t)64 * K_DIM;
            dst = smem_u32(&sA[buf][(lrow + 64) * LDT + lcol]);
            asm volatile("cp.async.cg.shared.global [%0], [%1], 16;\n" :: "r"(dst), "l"(src));
        }
        {
            const __nv_bfloat16* src = gB + (size_t)lrow * K_DIM + k0 + lcol;
            unsigned dst = smem_u32(&sB[buf][lrow * LDT + lcol]);
            asm volatile("cp.async.cg.shared.global [%0], [%1], 16;\n" :: "r"(dst), "l"(src));
            src += (size_t)64 * K_DIM;
            dst = smem_u32(&sB[buf][(lrow + 64) * LDT + lcol]);
            asm volatile("cp.async.cg.shared.global [%0], [%1], 16;\n" :: "r"(dst), "l"(src));
        }
    };

    constexpr int KT = K_DIM / BK;  // 128

    load_tile(0, 0);
    asm volatile("cp.async.commit_group;\n");

    for (int kt = 0; kt < KT; ++kt) {
        if (kt + 1 < KT) {
            load_tile(kt + 1, (kt + 1) & 1);
            asm volatile("cp.async.commit_group;\n");
            asm volatile("cp.async.wait_group 1;\n");
        } else {
            asm volatile("cp.async.wait_group 0;\n");
        }
        __syncthreads();

        const int buf = kt & 1;
        #pragma unroll
        for (int ks = 0; ks < 2; ++ks) {
            unsigned a[4][4], bb[2][4];
            #pragma unroll
            for (int mi = 0; mi < 4; ++mi) {
                const __nv_bfloat16* p =
                    &sA[buf][(wm * 64 + mi * 16 + (lane & 15)) * LDT + ks * 16 + (lane >> 4) * 8];
                ldsm4(a[mi], smem_u32(p));
            }
            #pragma unroll
            for (int nj = 0; nj < 2; ++nj) {
                const __nv_bfloat16* p =
                    &sB[buf][(wn * 32 + nj * 16 + (lane & 7) + ((lane >> 4) << 3)) * LDT +
                             ks * 16 + ((lane >> 3) & 1) * 8];
                ldsm4(bb[nj], smem_u32(p));
            }
            #pragma unroll
            for (int mi = 0; mi < 4; ++mi)
                #pragma unroll
                for (int ni = 0; ni < 4; ++ni)
                    mma_bf16(acc[mi][ni], a[mi][0], a[mi][1], a[mi][2], a[mi][3],
                             bb[ni >> 1][(ni & 1) * 2], bb[ni >> 1][(ni & 1) * 2 + 1]);
        }
        __syncthreads();
    }

    // epilogue: out = (4*s_x*s_w)*acc + 4*b
    const float alpha = 4.0f * (g_absmax[0] / 127.0f) * (g_absmax[1] / 127.0f);

    #pragma unroll
    for (int mi = 0; mi < 4; ++mi) {
        const int r0 = bm0 + wm * 64 + mi * 16 + (lane >> 2);
        #pragma unroll
        for (int ni = 0; ni < 4; ++ni) {
            const int c0 = bn0 + wn * 32 + ni * 8 + (lane & 3) * 2;
            const float b0v = 4.0f * bias[c0];
            const float b1v = 4.0f * bias[c0 + 1];
            float* o0 = C + (size_t)r0 * N_DIM + c0;
            o0[0] = alpha * acc[mi][ni][0] + b0v;
            o0[1] = alpha * acc[mi][ni][1] + b1v;
            float* o1 = C + (size_t)(r0 + 8) * N_DIM + c0;
            o1[0] = alpha * acc[mi][ni][2] + b0v;
            o1[1] = alpha * acc[mi][ni][3] + b1v;
        }
    }
}

// ---------------- launch ----------------
extern "C" void kernel_launch(void* const* d_in, const int* in_sizes, int n_in,
                              void* d_out, int out_size) {
    const float* x = (const float*)d_in[0];
    const float* W = (const float*)d_in[1];
    const float* b = (const float*)d_in[2];
    float* out = (float*)d_out;

    const int n4x = (M_DIM * K_DIM) / 4;  // 8388608
    const int n4w = (N_DIM * K_DIM) / 4;  // 4194304

    init_kernel<<<1, 32>>>();
    absmax_kernel<<<2048, 256>>>((const float4*)x, n4x, 0);
    absmax_kernel<<<2048, 256>>>((const float4*)W, n4w, 1);
    quant_x_kernel<<<(n4x + 255) / 256, 256>>>((const float4*)x, n4x);
    quant_w_kernel<<<(n4w + 255) / 256, 256>>>((const float4*)W, n4w);

    dim3 grid(N_DIM / BN, M_DIM / BM);  // (32, 64): x-fast over N for B-tile L2 reuse
    gemm_kernel<<<grid, 256>>>(out, b);
}